// round 2
// baseline (speedup 1.0000x reference)
#include <cuda_runtime.h>
#include <cuda_bf16.h>
#include <cstdint>
#include <math.h>

// Problem constants
#define NROWS 1024
#define DDIM  512
#define NCLS  70722
#define NT    553            // ceil(NCLS/128)
#define CPAD  (NT*128)       // 70784
#define M_MARGIN 0.4f
#define H_SCALE  0.333f
#define S_SCALE  64.0f
#define EPS_M    0.001f
#define PI_F     3.14159265358979f
#define COS_CLIP 0.99999950f   // cos(0.001)

// GEMM tiling
#define BM 128
#define BN 128
#define BK 32
#define PAD 8
#define NKT (DDIM/BK)   // 16

// ---------------- device scratch (static: no allocations) ----------------
__device__ __nv_bfloat16 g_A[NROWS*DDIM];            // normalized x, bf16
__device__ __nv_bfloat16 g_W[(size_t)CPAD*DDIM];     // normalized weights, bf16 (~72.5MB)
__device__ float g_xnorm[NROWS];
__device__ float g_gang[NROWS];
__device__ float g_gadd[NROWS];
__device__ float g_pmax[(size_t)NROWS*NT];
__device__ float g_psum[(size_t)NROWS*NT];
__device__ float g_lab_plain[NROWS];
__device__ float g_lab_adj[NROWS];
__device__ float g_loss[NROWS];

// ---------------- helpers ----------------
__device__ __forceinline__ float warpReduceSum(float v) {
#pragma unroll
    for (int o = 16; o > 0; o >>= 1) v += __shfl_xor_sync(0xffffffffu, v, o);
    return v;
}

__device__ __forceinline__ uint32_t smem_u32(const void* p) {
    return (uint32_t)__cvta_generic_to_shared(p);
}

__device__ __forceinline__ void cp16(uint32_t s, const void* g) {
    asm volatile("cp.async.cg.shared.global [%0], [%1], 16;\n" :: "r"(s), "l"(g));
}

// combine two (max, sumexp) pairs
__device__ __forceinline__ void lse_combine(float& m, float& s, float om, float os) {
    float nm = fmaxf(m, om);
    s = s * __expf(m - nm) + os * __expf(om - nm);
    m = nm;
}

// ---------------- prep kernels ----------------
__global__ void prep_x_kernel(const float* __restrict__ x) {
    int row = blockIdx.x, tid = threadIdx.x;          // 128 threads
    const float4* xr = (const float4*)(x + (size_t)row * DDIM);
    float4 v = xr[tid];
    float s = v.x*v.x + v.y*v.y + v.z*v.z + v.w*v.w;
    __shared__ float red[4];
    s = warpReduceSum(s);
    if ((tid & 31) == 0) red[tid >> 5] = s;
    __syncthreads();
    float tot = red[0] + red[1] + red[2] + red[3];
    float nrm = sqrtf(tot);
    if (tid == 0) g_xnorm[row] = nrm;
    float inv = 1.0f / fmaxf(nrm, 1e-12f);
    __nv_bfloat162 h0 = __floats2bfloat162_rn(v.x*inv, v.y*inv);
    __nv_bfloat162 h1 = __floats2bfloat162_rn(v.z*inv, v.w*inv);
    uint2 pk;
    pk.x = *(unsigned*)&h0; pk.y = *(unsigned*)&h1;
    ((uint2*)g_A)[(size_t)row * (DDIM/4) + tid] = pk;
}

__global__ void prep_w_kernel(const float* __restrict__ w) {
    int row = blockIdx.x, tid = threadIdx.x;          // 128 threads, CPAD blocks
    uint2 pk;
    if (row < NCLS) {
        const float4* wr = (const float4*)(w + (size_t)row * DDIM);
        float4 v = wr[tid];
        float s = v.x*v.x + v.y*v.y + v.z*v.z + v.w*v.w;
        __shared__ float red[4];
        s = warpReduceSum(s);
        if ((tid & 31) == 0) red[tid >> 5] = s;
        __syncthreads();
        float tot = red[0] + red[1] + red[2] + red[3];
        float inv = 1.0f / fmaxf(sqrtf(tot), 1e-12f);
        __nv_bfloat162 h0 = __floats2bfloat162_rn(v.x*inv, v.y*inv);
        __nv_bfloat162 h1 = __floats2bfloat162_rn(v.z*inv, v.w*inv);
        pk.x = *(unsigned*)&h0; pk.y = *(unsigned*)&h1;
    } else {
        pk.x = 0u; pk.y = 0u;
    }
    ((uint2*)g_W)[(size_t)row * (DDIM/4) + tid] = pk;
}

__global__ void stats_kernel() {
    int tid = threadIdx.x;                            // 1024 threads
    float n = g_xnorm[tid];
    float s = fminf(fmaxf(fmaxf(n, 1e-8f), 0.001f), 100.0f);
    __shared__ float red[32];
    float t = warpReduceSum(s);
    if ((tid & 31) == 0) red[tid >> 5] = t;
    __syncthreads();
    if (tid < 32) { float v = red[tid]; v = warpReduceSum(v); if (tid == 0) red[0] = v; }
    __syncthreads();
    float mean = red[0] / (float)NROWS;
    float d = s - mean;
    __syncthreads();
    t = warpReduceSum(d * d);
    if ((tid & 31) == 0) red[tid >> 5] = t;
    __syncthreads();
    if (tid < 32) { float v = red[tid]; v = warpReduceSum(v); if (tid == 0) red[0] = v; }
    __syncthreads();
    float stdv = sqrtf(red[0] / (float)(NROWS - 1));   // ddof=1
    float ms = fminf(fmaxf(d / (stdv + EPS_M) * H_SCALE, -1.0f), 1.0f);
    g_gang[tid] = -M_MARGIN * ms;
    g_gadd[tid] = M_MARGIN + M_MARGIN * ms;
}

__global__ void label_kernel(const float* __restrict__ x,
                             const int* __restrict__ labels,
                             const float* __restrict__ w) {
    int i = blockIdx.x, tid = threadIdx.x;            // 128 threads
    int l = labels[i];
    l = max(0, min(l, NCLS - 1));                     // safety clamp (no-op for valid labels)
    const float4* xr = (const float4*)(x + (size_t)i * DDIM);
    const float4* wr = (const float4*)(w + (size_t)l * DDIM);
    float4 a = xr[tid], b = wr[tid];
    float dot = a.x*b.x + a.y*b.y + a.z*b.z + a.w*b.w;
    float wsq = b.x*b.x + b.y*b.y + b.z*b.z + b.w*b.w;
    __shared__ float rd[4], rw[4];
    dot = warpReduceSum(dot);
    wsq = warpReduceSum(wsq);
    if ((tid & 31) == 0) { rd[tid >> 5] = dot; rw[tid >> 5] = wsq; }
    __syncthreads();
    if (tid == 0) {
        float Dv = rd[0] + rd[1] + rd[2] + rd[3];
        float Wv = rw[0] + rw[1] + rw[2] + rw[3];
        float xn = fmaxf(g_xnorm[i], 1e-12f);
        float wn = fmaxf(sqrtf(Wv), 1e-12f);
        float c  = fminf(fmaxf(Dv / (xn * wn), -1.0f), 1.0f);
        float th = acosf(c);
        float plain = S_SCALE * cosf(fminf(fmaxf(th, EPS_M), PI_F - EPS_M));
        float thm = fminf(fmaxf(th + g_gang[i], EPS_M), PI_F - EPS_M);
        float adj = S_SCALE * (cosf(thm) - g_gadd[i]);
        g_lab_plain[i] = plain;
        g_lab_adj[i]   = adj;
    }
}

// ---------------- main fused GEMM + online LSE ----------------
__global__ void __launch_bounds__(256, 2) gemm_lse_kernel() {
    // grid: (8 m-tiles, 553 c-tiles); x fast so concurrent CTAs share B tiles in L2
    int mt = blockIdx.x, ct = blockIdx.y;
    int tid = threadIdx.x;
    int lane = tid & 31, warp = tid >> 5;
    int wm = warp & 3;        // 0..3 -> m offset
    int wn = warp >> 2;       // 0..1 -> n offset

    __shared__ __align__(16) __nv_bfloat16 sA[2][BM][BK + PAD];
    __shared__ __align__(16) __nv_bfloat16 sB[2][BN][BK + PAD];
    __shared__ float sMax[2][BM];
    __shared__ float sSum[2][BM];

    const int m0 = mt * BM;
    const int n0 = ct * BN;

    float acc[2][8][4];
#pragma unroll
    for (int i = 0; i < 2; i++)
#pragma unroll
        for (int j = 0; j < 8; j++)
#pragma unroll
            for (int k = 0; k < 4; k++) acc[i][j][k] = 0.0f;

    // loaders: each thread moves 2x16B for A and 2x16B for B per K-tile
    int ar = tid >> 2;            // 0..63
    int ac = (tid & 3) * 8;       // 0,8,16,24
    const __nv_bfloat16* gA = g_A + (size_t)(m0 + ar) * DDIM + ac;
    const __nv_bfloat16* gB = g_W + (size_t)(n0 + ar) * DDIM + ac;

#define LOAD_TILE(buf, kt) do {                                             \
        int _k0 = (kt) * BK;                                                \
        cp16(smem_u32(&sA[buf][ar     ][ac]), gA + _k0);                    \
        cp16(smem_u32(&sA[buf][ar + 64][ac]), gA + (size_t)64*DDIM + _k0);  \
        cp16(smem_u32(&sB[buf][ar     ][ac]), gB + _k0);                    \
        cp16(smem_u32(&sB[buf][ar + 64][ac]), gB + (size_t)64*DDIM + _k0);  \
        asm volatile("cp.async.commit_group;\n" ::);                        \
    } while (0)

    LOAD_TILE(0, 0);

    for (int kt = 0; kt < NKT; kt++) {
        if (kt + 1 < NKT) LOAD_TILE((kt + 1) & 1, kt + 1);
        else asm volatile("cp.async.commit_group;\n" ::);   // empty group so wait 1 == tile done
        asm volatile("cp.async.wait_group 1;\n" ::: "memory");
        __syncthreads();

        int buf = kt & 1;
#pragma unroll
        for (int kk = 0; kk < 2; kk++) {
            int kb = kk * 16 + (lane >> 4) * 8;
            uint32_t a_r[2][4];
#pragma unroll
            for (int mi = 0; mi < 2; mi++) {
                uint32_t addr = smem_u32(&sA[buf][wm*32 + mi*16 + (lane & 15)][kb]);
                asm volatile("ldmatrix.sync.aligned.m8n8.x4.shared.b16 {%0,%1,%2,%3}, [%4];"
                             : "=r"(a_r[mi][0]), "=r"(a_r[mi][1]), "=r"(a_r[mi][2]), "=r"(a_r[mi][3])
                             : "r"(addr));
            }
            uint32_t b_r[8][2];
#pragma unroll
            for (int nj = 0; nj < 4; nj++) {
                uint32_t addr = smem_u32(&sB[buf][wn*64 + nj*16 + (lane & 15)][kb]);
                uint32_t r0, r1, r2, r3;
                asm volatile("ldmatrix.sync.aligned.m8n8.x4.shared.b16 {%0,%1,%2,%3}, [%4];"
                             : "=r"(r0), "=r"(r1), "=r"(r2), "=r"(r3)
                             : "r"(addr));
                b_r[2*nj][0] = r0; b_r[2*nj+1][0] = r1;
                b_r[2*nj][1] = r2; b_r[2*nj+1][1] = r3;
            }
#pragma unroll
            for (int mi = 0; mi < 2; mi++)
#pragma unroll
                for (int ni = 0; ni < 8; ni++) {
                    asm volatile(
                        "mma.sync.aligned.m16n8k16.row.col.f32.bf16.bf16.f32 "
                        "{%0,%1,%2,%3}, {%4,%5,%6,%7}, {%8,%9}, {%0,%1,%2,%3};"
                        : "+f"(acc[mi][ni][0]), "+f"(acc[mi][ni][1]),
                          "+f"(acc[mi][ni][2]), "+f"(acc[mi][ni][3])
                        : "r"(a_r[mi][0]), "r"(a_r[mi][1]), "r"(a_r[mi][2]), "r"(a_r[mi][3]),
                          "r"(b_r[ni][0]), "r"(b_r[ni][1]));
                }
        }
        __syncthreads();
    }
#undef LOAD_TILE

    // ---- epilogue: clamp -> logits -> per-row online (max, sumexp) over this C-tile ----
#pragma unroll
    for (int mi = 0; mi < 2; mi++) {
#pragma unroll
        for (int half = 0; half < 2; half++) {
            int rw = wm*32 + mi*16 + half*8 + (lane >> 2);     // row within CTA
            float mx = -1e30f;
#pragma unroll
            for (int ni = 0; ni < 8; ni++)
#pragma unroll
                for (int e = 0; e < 2; e++) {
                    int nn = n0 + wn*64 + ni*8 + (lane & 3)*2 + e;
                    if (nn < NCLS) {
                        float lg = S_SCALE * fminf(fmaxf(acc[mi][ni][half*2 + e], -COS_CLIP), COS_CLIP);
                        mx = fmaxf(mx, lg);
                    }
                }
            float sm = 0.0f;
#pragma unroll
            for (int ni = 0; ni < 8; ni++)
#pragma unroll
                for (int e = 0; e < 2; e++) {
                    int nn = n0 + wn*64 + ni*8 + (lane & 3)*2 + e;
                    if (nn < NCLS) {
                        float lg = S_SCALE * fminf(fmaxf(acc[mi][ni][half*2 + e], -COS_CLIP), COS_CLIP);
                        sm += __expf(lg - mx);
                    }
                }
            // reduce across the 4 lanes of the quad (they share the same row)
#pragma unroll
            for (int o = 1; o < 4; o <<= 1) {
                float om = __shfl_xor_sync(0xffffffffu, mx, o);
                float os = __shfl_xor_sync(0xffffffffu, sm, o);
                lse_combine(mx, sm, om, os);
            }
            if ((lane & 3) == 0) { sMax[wn][rw] = mx; sSum[wn][rw] = sm; }
        }
    }
    __syncthreads();

    if (tid < BM) {
        float m = sMax[0][tid], s = sSum[0][tid];
        lse_combine(m, s, sMax[1][tid], sSum[1][tid]);
        int grow = m0 + tid;
        g_pmax[(size_t)grow * NT + ct] = m;
        g_psum[(size_t)grow * NT + ct] = s;
    }
}

// ---------------- final reductions ----------------
__global__ void reduce1_kernel() {
    int row = blockIdx.x, tid = threadIdx.x;   // 128 threads
    float mx = -1e30f, sm = 0.0f;
    for (int t = tid; t < NT; t += 128) {
        float m = g_pmax[(size_t)row * NT + t];
        float s = g_psum[(size_t)row * NT + t];
        lse_combine(mx, sm, m, s);
    }
#pragma unroll
    for (int o = 16; o > 0; o >>= 1) {
        float om = __shfl_xor_sync(0xffffffffu, mx, o);
        float os = __shfl_xor_sync(0xffffffffu, sm, o);
        lse_combine(mx, sm, om, os);
    }
    __shared__ float rm[4], rs[4];
    int lane = tid & 31, w = tid >> 5;
    if (lane == 0) { rm[w] = mx; rs[w] = sm; }
    __syncthreads();
    if (tid == 0) {
        float m = rm[0], s = rs[0];
        lse_combine(m, s, rm[1], rs[1]);
        lse_combine(m, s, rm[2], rs[2]);
        lse_combine(m, s, rm[3], rs[3]);
        // swap label's plain logit for its margin-adjusted logit in the denominator
        float plain = g_lab_plain[row], adj = g_lab_adj[row];
        float s2 = s - __expf(plain - m) + __expf(adj - m);
        float lse = m + __logf(s2);
        g_loss[row] = lse - adj;
    }
}

__global__ void reduce2_kernel(float* __restrict__ out) {
    int tid = threadIdx.x;    // 256 threads
    float s = 0.0f;
    for (int t = tid; t < NROWS; t += 256) s += g_loss[t];
    s = warpReduceSum(s);
    __shared__ float red[8];
    if ((tid & 31) == 0) red[tid >> 5] = s;
    __syncthreads();
    if (tid == 0) {
        float tot = 0.0f;
        for (int i = 0; i < 8; i++) tot += red[i];
        out[0] = tot / (float)NROWS;
    }
}

// ---------------- launch ----------------
extern "C" void kernel_launch(void* const* d_in, const int* in_sizes, int n_in,
                              void* d_out, int out_size) {
    const float* x      = (const float*)d_in[0];
    const int*   labels = (const int*)d_in[1];
    const float* w      = (const float*)d_in[2];
    float* out = (float*)d_out;

    prep_x_kernel<<<NROWS, 128>>>(x);
    stats_kernel<<<1, 1024>>>();
    prep_w_kernel<<<CPAD, 128>>>(w);
    label_kernel<<<NROWS, 128>>>(x, labels, w);
    gemm_lse_kernel<<<dim3(8, NT), 256>>>();
    reduce1_kernel<<<NROWS, 128>>>();
    reduce2_kernel<<<1, 256>>>(out);
}